// round 10
// baseline (speedup 1.0000x reference)
#include <cuda_runtime.h>
#include <cuda_bf16.h>
#include <math.h>

// Problem dims
constexpr int B = 64, T = 512, D = 512, H = 1024, L = 3;
constexpr int G = 3 * H;            // 3072
constexpr float EPS = 1e-5f;
constexpr int NB = 296;             // persistent grid: 2 CTAs/SM * 148 SMs

// ---------------------------------------------------------------------------
// Device scratch (allocation-free rule: static __device__ arrays)
// ---------------------------------------------------------------------------
__device__ float g_xg0 [(size_t)B * T * G];     // x@Wi0^T + bi0, rows = b*T+t
__device__ float g_xres[(size_t)B * T * H];     // x@Wres^T
__device__ float g_h   [(size_t)L * B * H];     // hidden state per layer
__device__ float g_hgp [(size_t)2 * L * B * G]; // hg split-K partials [s][l][B][G]
__device__ float g_xgp [(size_t)4 * B * G];     // xg split-K partials [s][B][G]

__device__ unsigned g_bar_count = 0;
__device__ unsigned g_bar_gen   = 0;

// ---------------------------------------------------------------------------
// Software grid barrier (all NB CTAs guaranteed co-resident by launch_bounds)
// ---------------------------------------------------------------------------
__device__ __forceinline__ void grid_sync_()
{
    __syncthreads();
    if (threadIdx.x == 0) {
        unsigned gen;
        asm volatile("ld.acquire.gpu.u32 %0, [%1];" : "=r"(gen) : "l"(&g_bar_gen) : "memory");
        __threadfence();
        unsigned tk = atomicAdd(&g_bar_count, 1u);
        if (tk == NB - 1) {
            g_bar_count = 0;
            __threadfence();
            atomicAdd(&g_bar_gen, 1u);
        } else {
            unsigned cur;
            do {
                asm volatile("ld.acquire.gpu.u32 %0, [%1];" : "=r"(cur) : "l"(&g_bar_gen) : "memory");
            } while (cur == gen);
        }
    }
    __syncthreads();
}

// ---------------------------------------------------------------------------
// 64x64 fp32 GEMM tile, 256 threads, BK=16, 4x4 microtile.
// C[0..64, 0..64) (+=nothing) = A[64, klen] * W[64, klen]^T
// A, W already offset to (row0, k0); C offset to (row0, n0).
// ---------------------------------------------------------------------------
__device__ __forceinline__ void gemm_tile(
    const float* __restrict__ A, int lda,
    const float* __restrict__ W, int ldw,
    const float* __restrict__ bias,     // may be null; indexed [tn..] local
    float* __restrict__ C, int ldc,
    int klen,
    float (*sA)[68], float (*sW)[68])
{
    const int tid  = threadIdx.x;
    const int lrow = tid >> 2;            // 0..63
    const int lk   = (tid & 3) << 2;      // 0,4,8,12
    const int tm   = (tid & 15) << 2;     // m base
    const int tn   = (tid >> 4) << 2;     // n base

    float acc[4][4];
#pragma unroll
    for (int i = 0; i < 4; i++)
#pragma unroll
        for (int j = 0; j < 4; j++) acc[i][j] = 0.f;

    const float* Ap = A + (size_t)lrow * lda + lk;
    const float* Wp = W + (size_t)lrow * ldw + lk;

    for (int k0 = 0; k0 < klen; k0 += 16) {
        float4 va = *(const float4*)(Ap + k0);
        float4 vw = *(const float4*)(Wp + k0);
        __syncthreads();
        sA[lk + 0][lrow] = va.x; sA[lk + 1][lrow] = va.y;
        sA[lk + 2][lrow] = va.z; sA[lk + 3][lrow] = va.w;
        sW[lk + 0][lrow] = vw.x; sW[lk + 1][lrow] = vw.y;
        sW[lk + 2][lrow] = vw.z; sW[lk + 3][lrow] = vw.w;
        __syncthreads();
#pragma unroll
        for (int kk = 0; kk < 16; kk++) {
            float4 a = *(const float4*)&sA[kk][tm];
            float4 w = *(const float4*)&sW[kk][tn];
            float av[4] = {a.x, a.y, a.z, a.w};
            float wv[4] = {w.x, w.y, w.z, w.w};
#pragma unroll
            for (int i = 0; i < 4; i++)
#pragma unroll
                for (int j = 0; j < 4; j++)
                    acc[i][j] = fmaf(av[i], wv[j], acc[i][j]);
        }
    }

#pragma unroll
    for (int i = 0; i < 4; i++) {
#pragma unroll
        for (int j = 0; j < 4; j++) {
            float v = acc[i][j];
            if (bias) v += bias[tn + j];
            C[(size_t)(tm + i) * ldc + tn + j] = v;
        }
    }
}

// ---------------------------------------------------------------------------
// Precompute GEMM: C[M,N] = A[M,K] @ W[N,K]^T (+bias). grid = (N/64, M/64)
// ---------------------------------------------------------------------------
__global__ __launch_bounds__(256, 2) void gemm_pre(
    const float* __restrict__ A, int K,
    const float* __restrict__ W,
    const float* __restrict__ bias,
    float* __restrict__ C, int N)
{
    __shared__ float sA[16][68];
    __shared__ float sW[16][68];
    const int n0 = blockIdx.x * 64;
    const int m0 = blockIdx.y * 64;
    gemm_tile(A + (size_t)m0 * K, K,
              W + (size_t)n0 * K, K,
              bias ? bias + n0 : nullptr,
              C + (size_t)m0 * N + n0, N,
              K, sA, sW);
}

// ---------------------------------------------------------------------------
// Block reduce for LN stats (operates on up to 4 values simultaneously)
// ---------------------------------------------------------------------------
__device__ __forceinline__ void block_reduce(float* vals, int nvals,
                                             float* sred, float* bc)
{
    const int lane = threadIdx.x & 31;
    const int warp = threadIdx.x >> 5;
    for (int v = 0; v < nvals; v++) {
        float x = vals[v];
#pragma unroll
        for (int o = 16; o > 0; o >>= 1) x += __shfl_xor_sync(0xffffffffu, x, o);
        if (lane == 0) sred[warp * 4 + v] = x;
    }
    __syncthreads();
    if (threadIdx.x == 0) {
        for (int v = 0; v < nvals; v++) {
            float s = 0.f;
            for (int w = 0; w < 8; w++) s += sred[w * 4 + v];
            bc[v] = s;
        }
    }
    __syncthreads();
    for (int v = 0; v < nvals; v++) vals[v] = bc[v];
    __syncthreads();
}

// ---------------------------------------------------------------------------
// GRU cell + per-gate LayerNorm for one (layer, batch-row, t). 256 threads.
// ---------------------------------------------------------------------------
__device__ void cell_do(
    int l, int b, int t,
    const float* __restrict__ bi, const float* __restrict__ bh,
    const float* __restrict__ g_r_, const float* __restrict__ b_r_,
    const float* __restrict__ g_z_, const float* __restrict__ b_z_,
    const float* __restrict__ g_n_, const float* __restrict__ b_n_,
    float* __restrict__ out,
    float* sred, float* bc)
{
    const int tid = threadIdx.x;
    const float invH = 1.0f / (float)H;
    const float* gr = g_r_ + l * H; const float* br = b_r_ + l * H;
    const float* gz = g_z_ + l * H; const float* bz = b_z_ + l * H;
    const float* gn = g_n_ + l * H; const float* bn = b_n_ + l * H;
    const float* bhl = bh + l * G;
    const float* bil = bi + l * G;

    float vr[4], vz[4], xn[4], hn[4];
    float sums[4] = {0.f, 0.f, 0.f, 0.f};

#pragma unroll
    for (int i = 0; i < 4; i++) {
        int j = tid + i * 256;
        float xr, xz, xnn;
        if (l == 0) {
            const float* xA = g_xg0 + ((size_t)b * T + t) * G;
            xr = xA[j]; xz = xA[H + j]; xnn = xA[2 * H + j];   // bi0 baked in
        } else {
            xr = bil[j]; xz = bil[H + j]; xnn = bil[2 * H + j];
#pragma unroll
            for (int s = 0; s < 4; s++) {
                const float* xp = g_xgp + ((size_t)s * B + b) * G;
                xr += xp[j]; xz += xp[H + j]; xnn += xp[2 * H + j];
            }
        }
        const float* h0p = g_hgp + ((size_t)(0 * L + l) * B + b) * G;
        const float* h1p = g_hgp + ((size_t)(1 * L + l) * B + b) * G;
        float hr = h0p[j] + h1p[j] + bhl[j];
        float hz = h0p[H + j] + h1p[H + j] + bhl[H + j];
        float hnn = h0p[2 * H + j] + h1p[2 * H + j] + bhl[2 * H + j];

        float r_ = xr + hr;
        float z_ = xz + hz;
        vr[i] = r_; vz[i] = z_; xn[i] = xnn; hn[i] = hnn;
        sums[0] += r_; sums[1] += r_ * r_;
        sums[2] += z_; sums[3] += z_ * z_;
    }
    block_reduce(sums, 4, sred, bc);
    float mr = sums[0] * invH;
    float rstdr = rsqrtf(fmaxf(sums[1] * invH - mr * mr, 0.f) + EPS);
    float mz = sums[2] * invH;
    float rstdz = rsqrtf(fmaxf(sums[3] * invH - mz * mz, 0.f) + EPS);

    float z4[4];
    float sums2[4] = {0.f, 0.f, 0.f, 0.f};
#pragma unroll
    for (int i = 0; i < 4; i++) {
        int j = tid + i * 256;
        float rln = (vr[i] - mr) * rstdr * gr[j] + br[j];
        float zln = (vz[i] - mz) * rstdz * gz[j] + bz[j];
        float r = 1.0f / (1.0f + expf(-rln));
        float z = 1.0f / (1.0f + expf(-zln));
        float vn = xn[i] + r * hn[i];
        vr[i] = vn;
        z4[i] = z;
        sums2[0] += vn; sums2[1] += vn * vn;
    }
    block_reduce(sums2, 2, sred, bc);
    float mn = sums2[0] * invH;
    float rstdn = rsqrtf(fmaxf(sums2[1] * invH - mn * mn, 0.f) + EPS);

    float* hrow = g_h + (size_t)l * B * H + (size_t)b * H;
#pragma unroll
    for (int i = 0; i < 4; i++) {
        int j = tid + i * 256;
        float n = tanhf((vr[i] - mn) * rstdn * gn[j] + bn[j]);
        float res;
        if (l == 0) res = g_xres[((size_t)b * T + t) * H + j];
        else        res = g_h[(size_t)(l - 1) * B * H + (size_t)b * H + j];
        float hv = (1.0f - z4[i]) * n + z4[i] * hrow[j] + res;
        hrow[j] = hv;
        if (l == 2) out[((size_t)b * T + t) * H + j] = hv;
    }
}

// ---------------------------------------------------------------------------
// Persistent recurrence kernel: whole T-loop, one launch. grid = NB x 256.
// ---------------------------------------------------------------------------
__global__ __launch_bounds__(256, 2) void gru_persistent(
    const float* __restrict__ Wh0, const float* __restrict__ WhR,
    const float* __restrict__ WiR,
    const float* __restrict__ bi, const float* __restrict__ bh,
    const float* __restrict__ g_r_, const float* __restrict__ b_r_,
    const float* __restrict__ g_z_, const float* __restrict__ b_z_,
    const float* __restrict__ g_n_, const float* __restrict__ b_n_,
    float* __restrict__ out)
{
    __shared__ float sA[16][68];
    __shared__ float sW[16][68];
    __shared__ float sred[32];
    __shared__ float bc[4];

    const int bx = blockIdx.x;

    for (int t = 0; t < T; t++) {
        // ---- stage A: hg partials for all 3 layers (288 tasks, split-K=2) ----
        if (bx < 288) {
            int s = bx & 1, q = bx >> 1;          // q: 0..143
            int l = q / 48, n0 = (q - l * 48) * 64;
            const float* A = g_h + (size_t)l * B * H + s * 512;
            const float* W = ((l == 0) ? Wh0 : WhR + (size_t)(l - 1) * G * H)
                             + (size_t)n0 * H + s * 512;
            float* C = g_hgp + (size_t)(s * L + l) * B * G + n0;
            gemm_tile(A, H, W, H, nullptr, C, G, 512, sA, sW);
        }
        grid_sync_();

        // ---- cell layer 0 ----
        if (bx < B) cell_do(0, bx, t, bi, bh, g_r_, b_r_, g_z_, b_z_, g_n_, b_n_, out, sred, bc);
        grid_sync_();

        // ---- xg for layer 1 (192 tasks, split-K=4) ----
        if (bx < 192) {
            int s = bx & 3, q = bx >> 2;
            int n0 = q * 64;
            const float* A = g_h + 0 * (size_t)B * H + s * 256;
            const float* W = WiR + 0 * (size_t)G * H + (size_t)n0 * H + s * 256;
            float* C = g_xgp + (size_t)s * B * G + n0;
            gemm_tile(A, H, W, H, nullptr, C, G, 256, sA, sW);
        }
        grid_sync_();

        // ---- cell layer 1 ----
        if (bx < B) cell_do(1, bx, t, bi, bh, g_r_, b_r_, g_z_, b_z_, g_n_, b_n_, out, sred, bc);
        grid_sync_();

        // ---- xg for layer 2 ----
        if (bx < 192) {
            int s = bx & 3, q = bx >> 2;
            int n0 = q * 64;
            const float* A = g_h + 1 * (size_t)B * H + s * 256;
            const float* W = WiR + 1 * (size_t)G * H + (size_t)n0 * H + s * 256;
            float* C = g_xgp + (size_t)s * B * G + n0;
            gemm_tile(A, H, W, H, nullptr, C, G, 256, sA, sW);
        }
        grid_sync_();

        // ---- cell layer 2 (writes output row) ----
        if (bx < B) cell_do(2, bx, t, bi, bh, g_r_, b_r_, g_z_, b_z_, g_n_, b_n_, out, sred, bc);
        grid_sync_();
    }
}

// ---------------------------------------------------------------------------
// Launch
// ---------------------------------------------------------------------------
extern "C" void kernel_launch(void* const* d_in, const int* in_sizes, int n_in,
                              void* d_out, int out_size)
{
    const float* x    = (const float*)d_in[0];   // [B,T,D]
    const float* h0   = (const float*)d_in[1];   // [L,B,H]
    const float* Wi0  = (const float*)d_in[2];   // [3H,D]
    const float* Wh0  = (const float*)d_in[3];   // [3H,H]
    const float* Wi   = (const float*)d_in[4];   // [L-1,3H,H]
    const float* Wh   = (const float*)d_in[5];   // [L-1,3H,H]
    const float* bi   = (const float*)d_in[6];   // [L,3H]
    const float* bh   = (const float*)d_in[7];   // [L,3H]
    const float* g_r  = (const float*)d_in[8];
    const float* b_r  = (const float*)d_in[9];
    const float* g_z  = (const float*)d_in[10];
    const float* b_z  = (const float*)d_in[11];
    const float* g_n  = (const float*)d_in[12];
    const float* b_n  = (const float*)d_in[13];
    const float* Wres = (const float*)d_in[14];  // [H,D]
    float* out = (float*)d_out;                  // [B,T,H] then [L,B,H]

    float *xg0, *xres, *h;
    cudaGetSymbolAddress((void**)&xg0,  g_xg0);
    cudaGetSymbolAddress((void**)&xres, g_xres);
    cudaGetSymbolAddress((void**)&h,    g_h);

    // init hidden state
    cudaMemcpyAsync(h, h0, (size_t)L * B * H * sizeof(float),
                    cudaMemcpyDeviceToDevice);

    // precompute: xg0 = x @ Wi0^T + bi[0]  and  xres = x @ Wres^T
    gemm_pre<<<dim3(G / 64, (B * T) / 64), 256>>>(x, D, Wi0, bi, xg0, G);
    gemm_pre<<<dim3(H / 64, (B * T) / 64), 256>>>(x, D, Wres, nullptr, xres, H);

    // full recurrence in one persistent kernel
    gru_persistent<<<NB, 256>>>(Wh0, Wh, Wi, bi, bh,
                                g_r, b_r, g_z, b_z, g_n, b_n, out);

    // h_final
    cudaMemcpyAsync(out + (size_t)B * T * H, h,
                    (size_t)L * B * H * sizeof(float),
                    cudaMemcpyDeviceToDevice);
}

// round 11
// speedup vs baseline: 1.0080x; 1.0080x over previous
#include <cuda_runtime.h>
#include <cuda_bf16.h>
#include <math.h>

// Problem dims
constexpr int B = 64, T = 512, D = 512, H = 1024, L = 3;
constexpr int G = 3 * H;            // 3072
constexpr float EPS = 1e-5f;
constexpr int NB = 296;             // persistent grid: 2 CTAs/SM * 148 SMs

// ---------------------------------------------------------------------------
// Device scratch (allocation-free rule: static __device__ arrays)
// ---------------------------------------------------------------------------
__device__ float g_xg0 [(size_t)B * T * G];     // x@Wi0^T + bi0, rows = b*T+t
__device__ float g_xres[(size_t)B * T * H];     // x@Wres^T
__device__ float g_h   [(size_t)L * B * H];     // hidden state per layer
__device__ float g_hgp [(size_t)2 * L * B * G]; // hg split-K partials [s][l][B][G]
__device__ float g_xgp [(size_t)4 * B * G];     // xg split-K partials [s][B][G]

__device__ unsigned g_bar_count = 0;
__device__ unsigned g_bar_gen   = 0;

// ---------------------------------------------------------------------------
// Software grid barrier (all NB CTAs guaranteed co-resident by launch_bounds)
// ---------------------------------------------------------------------------
__device__ __forceinline__ void grid_sync_()
{
    __syncthreads();
    if (threadIdx.x == 0) {
        unsigned gen;
        asm volatile("ld.acquire.gpu.u32 %0, [%1];" : "=r"(gen) : "l"(&g_bar_gen) : "memory");
        __threadfence();
        unsigned tk = atomicAdd(&g_bar_count, 1u);
        if (tk == NB - 1) {
            g_bar_count = 0;
            __threadfence();
            atomicAdd(&g_bar_gen, 1u);
        } else {
            unsigned cur;
            do {
                asm volatile("ld.acquire.gpu.u32 %0, [%1];" : "=r"(cur) : "l"(&g_bar_gen) : "memory");
            } while (cur == gen);
        }
    }
    __syncthreads();
}

// ---------------------------------------------------------------------------
// 64x64 fp32 GEMM tile, 256 threads, BK=16, 4x4 microtile.
// C[0..64, 0..64) (+=nothing) = A[64, klen] * W[64, klen]^T
// A, W already offset to (row0, k0); C offset to (row0, n0).
// ---------------------------------------------------------------------------
__device__ __forceinline__ void gemm_tile(
    const float* __restrict__ A, int lda,
    const float* __restrict__ W, int ldw,
    const float* __restrict__ bias,     // may be null; indexed [tn..] local
    float* __restrict__ C, int ldc,
    int klen,
    float (*sA)[68], float (*sW)[68])
{
    const int tid  = threadIdx.x;
    const int lrow = tid >> 2;            // 0..63
    const int lk   = (tid & 3) << 2;      // 0,4,8,12
    const int tm   = (tid & 15) << 2;     // m base
    const int tn   = (tid >> 4) << 2;     // n base

    float acc[4][4];
#pragma unroll
    for (int i = 0; i < 4; i++)
#pragma unroll
        for (int j = 0; j < 4; j++) acc[i][j] = 0.f;

    const float* Ap = A + (size_t)lrow * lda + lk;
    const float* Wp = W + (size_t)lrow * ldw + lk;

    for (int k0 = 0; k0 < klen; k0 += 16) {
        float4 va = *(const float4*)(Ap + k0);
        float4 vw = *(const float4*)(Wp + k0);
        __syncthreads();
        sA[lk + 0][lrow] = va.x; sA[lk + 1][lrow] = va.y;
        sA[lk + 2][lrow] = va.z; sA[lk + 3][lrow] = va.w;
        sW[lk + 0][lrow] = vw.x; sW[lk + 1][lrow] = vw.y;
        sW[lk + 2][lrow] = vw.z; sW[lk + 3][lrow] = vw.w;
        __syncthreads();
#pragma unroll
        for (int kk = 0; kk < 16; kk++) {
            float4 a = *(const float4*)&sA[kk][tm];
            float4 w = *(const float4*)&sW[kk][tn];
            float av[4] = {a.x, a.y, a.z, a.w};
            float wv[4] = {w.x, w.y, w.z, w.w};
#pragma unroll
            for (int i = 0; i < 4; i++)
#pragma unroll
                for (int j = 0; j < 4; j++)
                    acc[i][j] = fmaf(av[i], wv[j], acc[i][j]);
        }
    }

#pragma unroll
    for (int i = 0; i < 4; i++) {
#pragma unroll
        for (int j = 0; j < 4; j++) {
            float v = acc[i][j];
            if (bias) v += bias[tn + j];
            C[(size_t)(tm + i) * ldc + tn + j] = v;
        }
    }
}

// ---------------------------------------------------------------------------
// Precompute GEMM: C[M,N] = A[M,K] @ W[N,K]^T (+bias). grid = (N/64, M/64)
// ---------------------------------------------------------------------------
__global__ __launch_bounds__(256, 2) void gemm_pre(
    const float* __restrict__ A, int K,
    const float* __restrict__ W,
    const float* __restrict__ bias,
    float* __restrict__ C, int N)
{
    __shared__ float sA[16][68];
    __shared__ float sW[16][68];
    const int n0 = blockIdx.x * 64;
    const int m0 = blockIdx.y * 64;
    gemm_tile(A + (size_t)m0 * K, K,
              W + (size_t)n0 * K, K,
              bias ? bias + n0 : nullptr,
              C + (size_t)m0 * N + n0, N,
              K, sA, sW);
}

// ---------------------------------------------------------------------------
// Block reduce for LN stats (operates on up to 4 values simultaneously)
// ---------------------------------------------------------------------------
__device__ __forceinline__ void block_reduce(float* vals, int nvals,
                                             float* sred, float* bc)
{
    const int lane = threadIdx.x & 31;
    const int warp = threadIdx.x >> 5;
    for (int v = 0; v < nvals; v++) {
        float x = vals[v];
#pragma unroll
        for (int o = 16; o > 0; o >>= 1) x += __shfl_xor_sync(0xffffffffu, x, o);
        if (lane == 0) sred[warp * 4 + v] = x;
    }
    __syncthreads();
    if (threadIdx.x == 0) {
        for (int v = 0; v < nvals; v++) {
            float s = 0.f;
            for (int w = 0; w < 8; w++) s += sred[w * 4 + v];
            bc[v] = s;
        }
    }
    __syncthreads();
    for (int v = 0; v < nvals; v++) vals[v] = bc[v];
    __syncthreads();
}

// ---------------------------------------------------------------------------
// GRU cell + per-gate LayerNorm for one (layer, batch-row, t). 256 threads.
// ---------------------------------------------------------------------------
__device__ void cell_do(
    int l, int b, int t,
    const float* __restrict__ bi, const float* __restrict__ bh,
    const float* __restrict__ g_r_, const float* __restrict__ b_r_,
    const float* __restrict__ g_z_, const float* __restrict__ b_z_,
    const float* __restrict__ g_n_, const float* __restrict__ b_n_,
    float* __restrict__ out,
    float* sred, float* bc)
{
    const int tid = threadIdx.x;
    const float invH = 1.0f / (float)H;
    const float* gr = g_r_ + l * H; const float* br = b_r_ + l * H;
    const float* gz = g_z_ + l * H; const float* bz = b_z_ + l * H;
    const float* gn = g_n_ + l * H; const float* bn = b_n_ + l * H;
    const float* bhl = bh + l * G;
    const float* bil = bi + l * G;

    float vr[4], vz[4], xn[4], hn[4];
    float sums[4] = {0.f, 0.f, 0.f, 0.f};

#pragma unroll
    for (int i = 0; i < 4; i++) {
        int j = tid + i * 256;
        float xr, xz, xnn;
        if (l == 0) {
            const float* xA = g_xg0 + ((size_t)b * T + t) * G;
            xr = xA[j]; xz = xA[H + j]; xnn = xA[2 * H + j];   // bi0 baked in
        } else {
            xr = bil[j]; xz = bil[H + j]; xnn = bil[2 * H + j];
#pragma unroll
            for (int s = 0; s < 4; s++) {
                const float* xp = g_xgp + ((size_t)s * B + b) * G;
                xr += xp[j]; xz += xp[H + j]; xnn += xp[2 * H + j];
            }
        }
        const float* h0p = g_hgp + ((size_t)(0 * L + l) * B + b) * G;
        const float* h1p = g_hgp + ((size_t)(1 * L + l) * B + b) * G;
        float hr = h0p[j] + h1p[j] + bhl[j];
        float hz = h0p[H + j] + h1p[H + j] + bhl[H + j];
        float hnn = h0p[2 * H + j] + h1p[2 * H + j] + bhl[2 * H + j];

        float r_ = xr + hr;
        float z_ = xz + hz;
        vr[i] = r_; vz[i] = z_; xn[i] = xnn; hn[i] = hnn;
        sums[0] += r_; sums[1] += r_ * r_;
        sums[2] += z_; sums[3] += z_ * z_;
    }
    block_reduce(sums, 4, sred, bc);
    float mr = sums[0] * invH;
    float rstdr = rsqrtf(fmaxf(sums[1] * invH - mr * mr, 0.f) + EPS);
    float mz = sums[2] * invH;
    float rstdz = rsqrtf(fmaxf(sums[3] * invH - mz * mz, 0.f) + EPS);

    float z4[4];
    float sums2[4] = {0.f, 0.f, 0.f, 0.f};
#pragma unroll
    for (int i = 0; i < 4; i++) {
        int j = tid + i * 256;
        float rln = (vr[i] - mr) * rstdr * gr[j] + br[j];
        float zln = (vz[i] - mz) * rstdz * gz[j] + bz[j];
        float r = 1.0f / (1.0f + expf(-rln));
        float z = 1.0f / (1.0f + expf(-zln));
        float vn = xn[i] + r * hn[i];
        vr[i] = vn;
        z4[i] = z;
        sums2[0] += vn; sums2[1] += vn * vn;
    }
    block_reduce(sums2, 2, sred, bc);
    float mn = sums2[0] * invH;
    float rstdn = rsqrtf(fmaxf(sums2[1] * invH - mn * mn, 0.f) + EPS);

    float* hrow = g_h + (size_t)l * B * H + (size_t)b * H;
#pragma unroll
    for (int i = 0; i < 4; i++) {
        int j = tid + i * 256;
        float n = tanhf((vr[i] - mn) * rstdn * gn[j] + bn[j]);
        float res;
        if (l == 0) res = g_xres[((size_t)b * T + t) * H + j];
        else        res = g_h[(size_t)(l - 1) * B * H + (size_t)b * H + j];
        float hv = (1.0f - z4[i]) * n + z4[i] * hrow[j] + res;
        hrow[j] = hv;
        if (l == 2) out[((size_t)b * T + t) * H + j] = hv;
    }
}

// ---------------------------------------------------------------------------
// Persistent recurrence kernel: whole T-loop, one launch. grid = NB x 256.
// ---------------------------------------------------------------------------
__global__ __launch_bounds__(256, 2) void gru_persistent(
    const float* __restrict__ Wh0, const float* __restrict__ WhR,
    const float* __restrict__ WiR,
    const float* __restrict__ bi, const float* __restrict__ bh,
    const float* __restrict__ g_r_, const float* __restrict__ b_r_,
    const float* __restrict__ g_z_, const float* __restrict__ b_z_,
    const float* __restrict__ g_n_, const float* __restrict__ b_n_,
    float* __restrict__ out)
{
    __shared__ float sA[16][68];
    __shared__ float sW[16][68];
    __shared__ float sred[32];
    __shared__ float bc[4];

    const int bx = blockIdx.x;

    for (int t = 0; t < T; t++) {
        // ---- stage A: hg partials for all 3 layers (288 tasks, split-K=2) ----
        if (bx < 288) {
            int s = bx & 1, q = bx >> 1;          // q: 0..143
            int l = q / 48, n0 = (q - l * 48) * 64;
            const float* A = g_h + (size_t)l * B * H + s * 512;
            const float* W = ((l == 0) ? Wh0 : WhR + (size_t)(l - 1) * G * H)
                             + (size_t)n0 * H + s * 512;
            float* C = g_hgp + (size_t)(s * L + l) * B * G + n0;
            gemm_tile(A, H, W, H, nullptr, C, G, 512, sA, sW);
        }
        grid_sync_();

        // ---- cell layer 0 ----
        if (bx < B) cell_do(0, bx, t, bi, bh, g_r_, b_r_, g_z_, b_z_, g_n_, b_n_, out, sred, bc);
        grid_sync_();

        // ---- xg for layer 1 (192 tasks, split-K=4) ----
        if (bx < 192) {
            int s = bx & 3, q = bx >> 2;
            int n0 = q * 64;
            const float* A = g_h + 0 * (size_t)B * H + s * 256;
            const float* W = WiR + 0 * (size_t)G * H + (size_t)n0 * H + s * 256;
            float* C = g_xgp + (size_t)s * B * G + n0;
            gemm_tile(A, H, W, H, nullptr, C, G, 256, sA, sW);
        }
        grid_sync_();

        // ---- cell layer 1 ----
        if (bx < B) cell_do(1, bx, t, bi, bh, g_r_, b_r_, g_z_, b_z_, g_n_, b_n_, out, sred, bc);
        grid_sync_();

        // ---- xg for layer 2 ----
        if (bx < 192) {
            int s = bx & 3, q = bx >> 2;
            int n0 = q * 64;
            const float* A = g_h + 1 * (size_t)B * H + s * 256;
            const float* W = WiR + 1 * (size_t)G * H + (size_t)n0 * H + s * 256;
            float* C = g_xgp + (size_t)s * B * G + n0;
            gemm_tile(A, H, W, H, nullptr, C, G, 256, sA, sW);
        }
        grid_sync_();

        // ---- cell layer 2 (writes output row) ----
        if (bx < B) cell_do(2, bx, t, bi, bh, g_r_, b_r_, g_z_, b_z_, g_n_, b_n_, out, sred, bc);
        grid_sync_();
    }
}

// ---------------------------------------------------------------------------
// Launch
// ---------------------------------------------------------------------------
extern "C" void kernel_launch(void* const* d_in, const int* in_sizes, int n_in,
                              void* d_out, int out_size)
{
    const float* x    = (const float*)d_in[0];   // [B,T,D]
    const float* h0   = (const float*)d_in[1];   // [L,B,H]
    const float* Wi0  = (const float*)d_in[2];   // [3H,D]
    const float* Wh0  = (const float*)d_in[3];   // [3H,H]
    const float* Wi   = (const float*)d_in[4];   // [L-1,3H,H]
    const float* Wh   = (const float*)d_in[5];   // [L-1,3H,H]
    const float* bi   = (const float*)d_in[6];   // [L,3H]
    const float* bh   = (const float*)d_in[7];   // [L,3H]
    const float* g_r  = (const float*)d_in[8];
    const float* b_r  = (const float*)d_in[9];
    const float* g_z  = (const float*)d_in[10];
    const float* b_z  = (const float*)d_in[11];
    const float* g_n  = (const float*)d_in[12];
    const float* b_n  = (const float*)d_in[13];
    const float* Wres = (const float*)d_in[14];  // [H,D]
    float* out = (float*)d_out;                  // [B,T,H] then [L,B,H]

    float *xg0, *xres, *h;
    cudaGetSymbolAddress((void**)&xg0,  g_xg0);
    cudaGetSymbolAddress((void**)&xres, g_xres);
    cudaGetSymbolAddress((void**)&h,    g_h);

    // init hidden state
    cudaMemcpyAsync(h, h0, (size_t)L * B * H * sizeof(float),
                    cudaMemcpyDeviceToDevice);

    // precompute: xg0 = x @ Wi0^T + bi[0]  and  xres = x @ Wres^T
    gemm_pre<<<dim3(G / 64, (B * T) / 64), 256>>>(x, D, Wi0, bi, xg0, G);
    gemm_pre<<<dim3(H / 64, (B * T) / 64), 256>>>(x, D, Wres, nullptr, xres, H);

    // full recurrence in one persistent kernel
    gru_persistent<<<NB, 256>>>(Wh0, Wh, Wi, bi, bh,
                                g_r, b_r, g_z, b_z, g_n, b_n, out);

    // h_final
    cudaMemcpyAsync(out + (size_t)B * T * H, h,
                    (size_t)L * B * H * sizeof(float),
                    cudaMemcpyDeviceToDevice);
}

// round 12
// speedup vs baseline: 1.0187x; 1.0106x over previous
#include <cuda_runtime.h>
#include <cuda_bf16.h>
#include <math.h>

// Problem dims
constexpr int B = 64, T = 512, D = 512, H = 1024, L = 3;
constexpr int G = 3 * H;            // 3072
constexpr float EPS = 1e-5f;
constexpr int NB = 296;             // persistent grid: 2 CTAs/SM * 148 SMs

// ---------------------------------------------------------------------------
// Device scratch (allocation-free rule: static __device__ arrays)
// ---------------------------------------------------------------------------
__device__ float g_xg0 [(size_t)B * T * G];     // x@Wi0^T + bi0, rows = b*T+t
__device__ float g_xres[(size_t)B * T * H];     // x@Wres^T
__device__ float g_h   [(size_t)L * B * H];     // hidden state per layer
__device__ float g_hgp [(size_t)2 * L * B * G]; // hg split-K partials [s][l][B][G]
__device__ float g_xgp [(size_t)4 * B * G];     // xg split-K partials [s][B][G]

__device__ unsigned g_bar_count = 0;
__device__ unsigned g_bar_gen   = 0;

// ---------------------------------------------------------------------------
// Software grid barrier (all NB CTAs guaranteed co-resident by launch_bounds)
// ---------------------------------------------------------------------------
__device__ __forceinline__ void grid_sync_()
{
    __syncthreads();
    if (threadIdx.x == 0) {
        unsigned gen;
        asm volatile("ld.acquire.gpu.u32 %0, [%1];" : "=r"(gen) : "l"(&g_bar_gen) : "memory");
        __threadfence();
        unsigned tk = atomicAdd(&g_bar_count, 1u);
        if (tk == NB - 1) {
            g_bar_count = 0;
            __threadfence();
            atomicAdd(&g_bar_gen, 1u);
        } else {
            unsigned cur;
            do {
                asm volatile("ld.acquire.gpu.u32 %0, [%1];" : "=r"(cur) : "l"(&g_bar_gen) : "memory");
            } while (cur == gen);
        }
    }
    __syncthreads();
}

// ---------------------------------------------------------------------------
// 64x64 fp32 GEMM tile, 256 threads, BK=16, 4x4 microtile.
// C[0..64, 0..64) (+=nothing) = A[64, klen] * W[64, klen]^T
// A, W already offset to (row0, k0); C offset to (row0, n0).
// ---------------------------------------------------------------------------
__device__ __forceinline__ void gemm_tile(
    const float* __restrict__ A, int lda,
    const float* __restrict__ W, int ldw,
    const float* __restrict__ bias,     // may be null; indexed [tn..] local
    float* __restrict__ C, int ldc,
    int klen,
    float (*sA)[68], float (*sW)[68])
{
    const int tid  = threadIdx.x;
    const int lrow = tid >> 2;            // 0..63
    const int lk   = (tid & 3) << 2;      // 0,4,8,12
    const int tm   = (tid & 15) << 2;     // m base
    const int tn   = (tid >> 4) << 2;     // n base

    float acc[4][4];
#pragma unroll
    for (int i = 0; i < 4; i++)
#pragma unroll
        for (int j = 0; j < 4; j++) acc[i][j] = 0.f;

    const float* Ap = A + (size_t)lrow * lda + lk;
    const float* Wp = W + (size_t)lrow * ldw + lk;

    for (int k0 = 0; k0 < klen; k0 += 16) {
        float4 va = *(const float4*)(Ap + k0);
        float4 vw = *(const float4*)(Wp + k0);
        __syncthreads();
        sA[lk + 0][lrow] = va.x; sA[lk + 1][lrow] = va.y;
        sA[lk + 2][lrow] = va.z; sA[lk + 3][lrow] = va.w;
        sW[lk + 0][lrow] = vw.x; sW[lk + 1][lrow] = vw.y;
        sW[lk + 2][lrow] = vw.z; sW[lk + 3][lrow] = vw.w;
        __syncthreads();
#pragma unroll
        for (int kk = 0; kk < 16; kk++) {
            float4 a = *(const float4*)&sA[kk][tm];
            float4 w = *(const float4*)&sW[kk][tn];
            float av[4] = {a.x, a.y, a.z, a.w};
            float wv[4] = {w.x, w.y, w.z, w.w};
#pragma unroll
            for (int i = 0; i < 4; i++)
#pragma unroll
                for (int j = 0; j < 4; j++)
                    acc[i][j] = fmaf(av[i], wv[j], acc[i][j]);
        }
    }

#pragma unroll
    for (int i = 0; i < 4; i++) {
#pragma unroll
        for (int j = 0; j < 4; j++) {
            float v = acc[i][j];
            if (bias) v += bias[tn + j];
            C[(size_t)(tm + i) * ldc + tn + j] = v;
        }
    }
}

// ---------------------------------------------------------------------------
// Precompute GEMM: C[M,N] = A[M,K] @ W[N,K]^T (+bias). grid = (N/64, M/64)
// ---------------------------------------------------------------------------
__global__ __launch_bounds__(256, 2) void gemm_pre(
    const float* __restrict__ A, int K,
    const float* __restrict__ W,
    const float* __restrict__ bias,
    float* __restrict__ C, int N)
{
    __shared__ float sA[16][68];
    __shared__ float sW[16][68];
    const int n0 = blockIdx.x * 64;
    const int m0 = blockIdx.y * 64;
    gemm_tile(A + (size_t)m0 * K, K,
              W + (size_t)n0 * K, K,
              bias ? bias + n0 : nullptr,
              C + (size_t)m0 * N + n0, N,
              K, sA, sW);
}

// ---------------------------------------------------------------------------
// Block reduce for LN stats (operates on up to 4 values simultaneously)
// ---------------------------------------------------------------------------
__device__ __forceinline__ void block_reduce(float* vals, int nvals,
                                             float* sred, float* bc)
{
    const int lane = threadIdx.x & 31;
    const int warp = threadIdx.x >> 5;
    for (int v = 0; v < nvals; v++) {
        float x = vals[v];
#pragma unroll
        for (int o = 16; o > 0; o >>= 1) x += __shfl_xor_sync(0xffffffffu, x, o);
        if (lane == 0) sred[warp * 4 + v] = x;
    }
    __syncthreads();
    if (threadIdx.x == 0) {
        for (int v = 0; v < nvals; v++) {
            float s = 0.f;
            for (int w = 0; w < 8; w++) s += sred[w * 4 + v];
            bc[v] = s;
        }
    }
    __syncthreads();
    for (int v = 0; v < nvals; v++) vals[v] = bc[v];
    __syncthreads();
}

// ---------------------------------------------------------------------------
// GRU cell + per-gate LayerNorm for one (layer, batch-row, t). 256 threads.
// ---------------------------------------------------------------------------
__device__ void cell_do(
    int l, int b, int t,
    const float* __restrict__ bi, const float* __restrict__ bh,
    const float* __restrict__ g_r_, const float* __restrict__ b_r_,
    const float* __restrict__ g_z_, const float* __restrict__ b_z_,
    const float* __restrict__ g_n_, const float* __restrict__ b_n_,
    float* __restrict__ out,
    float* sred, float* bc)
{
    const int tid = threadIdx.x;
    const float invH = 1.0f / (float)H;
    const float* gr = g_r_ + l * H; const float* br = b_r_ + l * H;
    const float* gz = g_z_ + l * H; const float* bz = b_z_ + l * H;
    const float* gn = g_n_ + l * H; const float* bn = b_n_ + l * H;
    const float* bhl = bh + l * G;
    const float* bil = bi + l * G;

    float vr[4], vz[4], xn[4], hn[4];
    float sums[4] = {0.f, 0.f, 0.f, 0.f};

#pragma unroll
    for (int i = 0; i < 4; i++) {
        int j = tid + i * 256;
        float xr, xz, xnn;
        if (l == 0) {
            const float* xA = g_xg0 + ((size_t)b * T + t) * G;
            xr = xA[j]; xz = xA[H + j]; xnn = xA[2 * H + j];   // bi0 baked in
        } else {
            xr = bil[j]; xz = bil[H + j]; xnn = bil[2 * H + j];
#pragma unroll
            for (int s = 0; s < 4; s++) {
                const float* xp = g_xgp + ((size_t)s * B + b) * G;
                xr += xp[j]; xz += xp[H + j]; xnn += xp[2 * H + j];
            }
        }
        const float* h0p = g_hgp + ((size_t)(0 * L + l) * B + b) * G;
        const float* h1p = g_hgp + ((size_t)(1 * L + l) * B + b) * G;
        float hr = h0p[j] + h1p[j] + bhl[j];
        float hz = h0p[H + j] + h1p[H + j] + bhl[H + j];
        float hnn = h0p[2 * H + j] + h1p[2 * H + j] + bhl[2 * H + j];

        float r_ = xr + hr;
        float z_ = xz + hz;
        vr[i] = r_; vz[i] = z_; xn[i] = xnn; hn[i] = hnn;
        sums[0] += r_; sums[1] += r_ * r_;
        sums[2] += z_; sums[3] += z_ * z_;
    }
    block_reduce(sums, 4, sred, bc);
    float mr = sums[0] * invH;
    float rstdr = rsqrtf(fmaxf(sums[1] * invH - mr * mr, 0.f) + EPS);
    float mz = sums[2] * invH;
    float rstdz = rsqrtf(fmaxf(sums[3] * invH - mz * mz, 0.f) + EPS);

    float z4[4];
    float sums2[4] = {0.f, 0.f, 0.f, 0.f};
#pragma unroll
    for (int i = 0; i < 4; i++) {
        int j = tid + i * 256;
        float rln = (vr[i] - mr) * rstdr * gr[j] + br[j];
        float zln = (vz[i] - mz) * rstdz * gz[j] + bz[j];
        float r = 1.0f / (1.0f + expf(-rln));
        float z = 1.0f / (1.0f + expf(-zln));
        float vn = xn[i] + r * hn[i];
        vr[i] = vn;
        z4[i] = z;
        sums2[0] += vn; sums2[1] += vn * vn;
    }
    block_reduce(sums2, 2, sred, bc);
    float mn = sums2[0] * invH;
    float rstdn = rsqrtf(fmaxf(sums2[1] * invH - mn * mn, 0.f) + EPS);

    float* hrow = g_h + (size_t)l * B * H + (size_t)b * H;
#pragma unroll
    for (int i = 0; i < 4; i++) {
        int j = tid + i * 256;
        float n = tanhf((vr[i] - mn) * rstdn * gn[j] + bn[j]);
        float res;
        if (l == 0) res = g_xres[((size_t)b * T + t) * H + j];
        else        res = g_h[(size_t)(l - 1) * B * H + (size_t)b * H + j];
        float hv = (1.0f - z4[i]) * n + z4[i] * hrow[j] + res;
        hrow[j] = hv;
        if (l == 2) out[((size_t)b * T + t) * H + j] = hv;
    }
}

// ---------------------------------------------------------------------------
// Persistent recurrence kernel: whole T-loop, one launch. grid = NB x 256.
// ---------------------------------------------------------------------------
__global__ __launch_bounds__(256, 2) void gru_persistent(
    const float* __restrict__ Wh0, const float* __restrict__ WhR,
    const float* __restrict__ WiR,
    const float* __restrict__ bi, const float* __restrict__ bh,
    const float* __restrict__ g_r_, const float* __restrict__ b_r_,
    const float* __restrict__ g_z_, const float* __restrict__ b_z_,
    const float* __restrict__ g_n_, const float* __restrict__ b_n_,
    float* __restrict__ out)
{
    __shared__ float sA[16][68];
    __shared__ float sW[16][68];
    __shared__ float sred[32];
    __shared__ float bc[4];

    const int bx = blockIdx.x;

    for (int t = 0; t < T; t++) {
        // ---- stage A: hg partials for all 3 layers (288 tasks, split-K=2) ----
        if (bx < 288) {
            int s = bx & 1, q = bx >> 1;          // q: 0..143
            int l = q / 48, n0 = (q - l * 48) * 64;
            const float* A = g_h + (size_t)l * B * H + s * 512;
            const float* W = ((l == 0) ? Wh0 : WhR + (size_t)(l - 1) * G * H)
                             + (size_t)n0 * H + s * 512;
            float* C = g_hgp + (size_t)(s * L + l) * B * G + n0;
            gemm_tile(A, H, W, H, nullptr, C, G, 512, sA, sW);
        }
        grid_sync_();

        // ---- cell layer 0 ----
        if (bx < B) cell_do(0, bx, t, bi, bh, g_r_, b_r_, g_z_, b_z_, g_n_, b_n_, out, sred, bc);
        grid_sync_();

        // ---- xg for layer 1 (192 tasks, split-K=4) ----
        if (bx < 192) {
            int s = bx & 3, q = bx >> 2;
            int n0 = q * 64;
            const float* A = g_h + 0 * (size_t)B * H + s * 256;
            const float* W = WiR + 0 * (size_t)G * H + (size_t)n0 * H + s * 256;
            float* C = g_xgp + (size_t)s * B * G + n0;
            gemm_tile(A, H, W, H, nullptr, C, G, 256, sA, sW);
        }
        grid_sync_();

        // ---- cell layer 1 ----
        if (bx < B) cell_do(1, bx, t, bi, bh, g_r_, b_r_, g_z_, b_z_, g_n_, b_n_, out, sred, bc);
        grid_sync_();

        // ---- xg for layer 2 ----
        if (bx < 192) {
            int s = bx & 3, q = bx >> 2;
            int n0 = q * 64;
            const float* A = g_h + 1 * (size_t)B * H + s * 256;
            const float* W = WiR + 1 * (size_t)G * H + (size_t)n0 * H + s * 256;
            float* C = g_xgp + (size_t)s * B * G + n0;
            gemm_tile(A, H, W, H, nullptr, C, G, 256, sA, sW);
        }
        grid_sync_();

        // ---- cell layer 2 (writes output row) ----
        if (bx < B) cell_do(2, bx, t, bi, bh, g_r_, b_r_, g_z_, b_z_, g_n_, b_n_, out, sred, bc);
        grid_sync_();
    }
}

// ---------------------------------------------------------------------------
// Launch
// ---------------------------------------------------------------------------
extern "C" void kernel_launch(void* const* d_in, const int* in_sizes, int n_in,
                              void* d_out, int out_size)
{
    const float* x    = (const float*)d_in[0];   // [B,T,D]
    const float* h0   = (const float*)d_in[1];   // [L,B,H]
    const float* Wi0  = (const float*)d_in[2];   // [3H,D]
    const float* Wh0  = (const float*)d_in[3];   // [3H,H]
    const float* Wi   = (const float*)d_in[4];   // [L-1,3H,H]
    const float* Wh   = (const float*)d_in[5];   // [L-1,3H,H]
    const float* bi   = (const float*)d_in[6];   // [L,3H]
    const float* bh   = (const float*)d_in[7];   // [L,3H]
    const float* g_r  = (const float*)d_in[8];
    const float* b_r  = (const float*)d_in[9];
    const float* g_z  = (const float*)d_in[10];
    const float* b_z  = (const float*)d_in[11];
    const float* g_n  = (const float*)d_in[12];
    const float* b_n  = (const float*)d_in[13];
    const float* Wres = (const float*)d_in[14];  // [H,D]
    float* out = (float*)d_out;                  // [B,T,H] then [L,B,H]

    float *xg0, *xres, *h;
    cudaGetSymbolAddress((void**)&xg0,  g_xg0);
    cudaGetSymbolAddress((void**)&xres, g_xres);
    cudaGetSymbolAddress((void**)&h,    g_h);

    // init hidden state
    cudaMemcpyAsync(h, h0, (size_t)L * B * H * sizeof(float),
                    cudaMemcpyDeviceToDevice);

    // precompute: xg0 = x @ Wi0^T + bi[0]  and  xres = x @ Wres^T
    gemm_pre<<<dim3(G / 64, (B * T) / 64), 256>>>(x, D, Wi0, bi, xg0, G);
    gemm_pre<<<dim3(H / 64, (B * T) / 64), 256>>>(x, D, Wres, nullptr, xres, H);

    // full recurrence in one persistent kernel
    gru_persistent<<<NB, 256>>>(Wh0, Wh, Wi, bi, bh,
                                g_r, b_r, g_z, b_z, g_n, b_n, out);

    // h_final
    cudaMemcpyAsync(out + (size_t)B * T * H, h,
                    (size_t)L * B * H * sizeof(float),
                    cudaMemcpyDeviceToDevice);
}